// round 1
// baseline (speedup 1.0000x reference)
#include <cuda_runtime.h>
#include <math.h>

namespace {
constexpr int Bc = 4, Sc = 1024, Ec = 512, Hc = 8, DKc = 64;
constexpr int M_TOT = Bc * Sc;  // 4096
}

// Scratch (device globals: allocation-free per harness rules)
__device__ float g_Q[(size_t)Bc * Hc * Sc * DKc];
__device__ float g_K[(size_t)Bc * Hc * Sc * DKc];
__device__ float g_V[(size_t)Bc * Hc * Sc * DKc];
__device__ float g_X[(size_t)Bc * Sc * Ec];

// ---------------------------------------------------------------------------
// Y = X * W^T + bias.  X:[M,E], W:[E,E] row-major (W[n][k]).
// SPLIT: write Y into head-split layout [B,H,S,DK]; else plain [M,E].
// Block: 256 threads, 64x64 tile, 4x4 micro-tile, BK=32.
// ---------------------------------------------------------------------------
template <bool SPLIT>
__global__ void __launch_bounds__(256) gemm_proj(const float* __restrict__ X,
                                                 const float* __restrict__ W,
                                                 const float* __restrict__ bias,
                                                 float* __restrict__ Y) {
    __shared__ float Xs[64][33];
    __shared__ float Ws[64][33];
    const int tid = threadIdx.x;
    const int tx = tid & 15, ty = tid >> 4;
    const int bm = blockIdx.y * 64, bn = blockIdx.x * 64;

    float acc[4][4] = {};

    for (int k0 = 0; k0 < Ec; k0 += 32) {
#pragma unroll
        for (int t = 0; t < 2; t++) {
            int idx = t * 256 + tid;          // 512 float4 slots per tile
            int r = idx >> 3, c = (idx & 7) << 2;
            float4 xv = *(const float4*)&X[(size_t)(bm + r) * Ec + k0 + c];
            Xs[r][c] = xv.x; Xs[r][c + 1] = xv.y; Xs[r][c + 2] = xv.z; Xs[r][c + 3] = xv.w;
            float4 wv = *(const float4*)&W[(size_t)(bn + r) * Ec + k0 + c];
            Ws[r][c] = wv.x; Ws[r][c + 1] = wv.y; Ws[r][c + 2] = wv.z; Ws[r][c + 3] = wv.w;
        }
        __syncthreads();
#pragma unroll
        for (int k = 0; k < 32; k++) {
            float a[4], w[4];
#pragma unroll
            for (int i = 0; i < 4; i++) a[i] = Xs[ty * 4 + i][k];
#pragma unroll
            for (int j = 0; j < 4; j++) w[j] = Ws[tx * 4 + j][k];
#pragma unroll
            for (int i = 0; i < 4; i++)
#pragma unroll
                for (int j = 0; j < 4; j++) acc[i][j] = fmaf(a[i], w[j], acc[i][j]);
        }
        __syncthreads();
    }

    const int n0 = bn + tx * 4;
    const float4 bv = *(const float4*)&bias[n0];
#pragma unroll
    for (int i = 0; i < 4; i++) {
        const int m = bm + ty * 4 + i;
        float4 o;
        o.x = acc[i][0] + bv.x;
        o.y = acc[i][1] + bv.y;
        o.z = acc[i][2] + bv.z;
        o.w = acc[i][3] + bv.w;
        if (SPLIT) {
            const int bIdx = m >> 10, s = m & (Sc - 1);
            const int h = n0 >> 6, d = n0 & 63;
            *(float4*)&Y[(((size_t)bIdx * Hc + h) * Sc + s) * DKc + d] = o;
        } else {
            *(float4*)&Y[(size_t)m * Ec + n0] = o;
        }
    }
}

// ---------------------------------------------------------------------------
// Fused attention: per block (b, h, q-tile of 64 rows), flash-style online
// softmax over 16 key-tiles of 64. Bias computed inline from dist_conv:
//   bias_g(d) = cb2[g] + sum_h cw2[g,h] * relu(d*cw1[h] + cb1[h])
// scores = (q.k / 8) * bias;  mask==0 -> -1e9.  Output written concatenated
// into [B,S,E] so the out-projection is a plain GEMM.
// Dynamic smem: Qs/Ks/Vs/Ps each [64][65] fp32 = 66560 B.
// ---------------------------------------------------------------------------
__global__ void __launch_bounds__(256) attn_kernel(
    const float* __restrict__ Qp, const float* __restrict__ Kp,
    const float* __restrict__ Vp, const float* __restrict__ dist,
    const int* __restrict__ mask,
    const float* __restrict__ cw1, const float* __restrict__ cb1,
    const float* __restrict__ cw2, const float* __restrict__ cb2,
    float* __restrict__ Xout) {
    extern __shared__ float sm[];
    float(*Qs)[65] = (float(*)[65])sm;
    float(*Ks)[65] = (float(*)[65])(sm + 64 * 65);
    float(*Vs)[65] = (float(*)[65])(sm + 2 * 64 * 65);
    float(*Ps)[65] = (float(*)[65])(sm + 3 * 64 * 65);

    const int tid = threadIdx.x;
    const int tx = tid & 15, ty = tid >> 4;
    const int b = blockIdx.z, h = blockIdx.y;
    const int q0 = blockIdx.x * 64;

    const float* Qbase = Qp + ((size_t)b * Hc + h) * Sc * DKc;
    const float* Kbase = Kp + ((size_t)b * Hc + h) * Sc * DKc;
    const float* Vbase = Vp + ((size_t)b * Hc + h) * Sc * DKc;

    float w1[8], b1[8], w2[8];
#pragma unroll
    for (int t = 0; t < 8; t++) {
        w1[t] = cw1[t];
        b1[t] = cb1[t];
        w2[t] = cw2[h * Hc + t];
    }
    const float c2 = cb2[h];

    // Load Q tile (64x64)
#pragma unroll
    for (int t = 0; t < 4; t++) {
        int idx = t * 256 + tid;
        int r = idx >> 4, c = (idx & 15) << 2;
        float4 v = *(const float4*)&Qbase[(size_t)(q0 + r) * DKc + c];
        Qs[r][c] = v.x; Qs[r][c + 1] = v.y; Qs[r][c + 2] = v.z; Qs[r][c + 3] = v.w;
    }

    float o[4][4] = {};
    float mrow[4], lrow[4];
#pragma unroll
    for (int i = 0; i < 4; i++) { mrow[i] = -INFINITY; lrow[i] = 0.f; }

    for (int k0 = 0; k0 < Sc; k0 += 64) {
        __syncthreads();  // prior PV reads of Ks/Vs/Ps complete
#pragma unroll
        for (int t = 0; t < 4; t++) {
            int idx = t * 256 + tid;
            int r = idx >> 4, c = (idx & 15) << 2;
            float4 kv = *(const float4*)&Kbase[(size_t)(k0 + r) * DKc + c];
            Ks[r][c] = kv.x; Ks[r][c + 1] = kv.y; Ks[r][c + 2] = kv.z; Ks[r][c + 3] = kv.w;
            float4 vv = *(const float4*)&Vbase[(size_t)(k0 + r) * DKc + c];
            Vs[r][c] = vv.x; Vs[r][c + 1] = vv.y; Vs[r][c + 2] = vv.z; Vs[r][c + 3] = vv.w;
        }
        __syncthreads();

        // S = Q * K^T  (4x4 per thread)
        float sc[4][4] = {};
#pragma unroll
        for (int k = 0; k < DKc; k++) {
            float a[4], kk[4];
#pragma unroll
            for (int i = 0; i < 4; i++) a[i] = Qs[ty * 4 + i][k];
#pragma unroll
            for (int j = 0; j < 4; j++) kk[j] = Ks[tx * 4 + j][k];
#pragma unroll
            for (int i = 0; i < 4; i++)
#pragma unroll
                for (int j = 0; j < 4; j++) sc[i][j] = fmaf(a[i], kk[j], sc[i][j]);
        }

        // scale * bias, mask
#pragma unroll
        for (int i = 0; i < 4; i++) {
            const int qi = q0 + ty * 4 + i;
            const size_t rowoff = ((size_t)b * Sc + qi) * Sc + k0 + tx * 4;
            float4 dv = *(const float4*)&dist[rowoff];
            int4 mv = *(const int4*)&mask[rowoff];
            float dd[4] = {dv.x, dv.y, dv.z, dv.w};
            int mm[4] = {mv.x, mv.y, mv.z, mv.w};
#pragma unroll
            for (int j = 0; j < 4; j++) {
                float bias = c2;
#pragma unroll
                for (int t = 0; t < 8; t++)
                    bias += w2[t] * fmaxf(fmaf(dd[j], w1[t], b1[t]), 0.f);
                float sv = sc[i][j] * 0.125f * bias;
                sc[i][j] = (mm[j] == 0) ? -1e9f : sv;
            }
        }

        // online softmax: rows split across 16 lanes (same warp half)
#pragma unroll
        for (int i = 0; i < 4; i++) {
            float mloc = fmaxf(fmaxf(sc[i][0], sc[i][1]), fmaxf(sc[i][2], sc[i][3]));
#pragma unroll
            for (int off = 8; off >= 1; off >>= 1)
                mloc = fmaxf(mloc, __shfl_xor_sync(0xffffffffu, mloc, off, 16));
            const float mnew = fmaxf(mrow[i], mloc);
            const float alpha = __expf(mrow[i] - mnew);
            mrow[i] = mnew;
            float rs = 0.f;
#pragma unroll
            for (int j = 0; j < 4; j++) {
                float p = __expf(sc[i][j] - mnew);
                Ps[ty * 4 + i][tx * 4 + j] = p;
                rs += p;
            }
#pragma unroll
            for (int off = 8; off >= 1; off >>= 1)
                rs += __shfl_xor_sync(0xffffffffu, rs, off, 16);
            lrow[i] = lrow[i] * alpha + rs;
#pragma unroll
            for (int j = 0; j < 4; j++) o[i][j] *= alpha;
        }
        __syncthreads();

        // O += P * V
#pragma unroll
        for (int k = 0; k < 64; k++) {
            float a[4], vv[4];
#pragma unroll
            for (int i = 0; i < 4; i++) a[i] = Ps[ty * 4 + i][k];
#pragma unroll
            for (int j = 0; j < 4; j++) vv[j] = Vs[k][tx * 4 + j];
#pragma unroll
            for (int i = 0; i < 4; i++)
#pragma unroll
                for (int j = 0; j < 4; j++) o[i][j] = fmaf(a[i], vv[j], o[i][j]);
        }
    }

    // epilogue: normalize, write concatenated [B,S,E]
#pragma unroll
    for (int i = 0; i < 4; i++) {
        const int qi = q0 + ty * 4 + i;
        const float inv = 1.f / lrow[i];
        float4 ov = {o[i][0] * inv, o[i][1] * inv, o[i][2] * inv, o[i][3] * inv};
        *(float4*)&Xout[((size_t)b * Sc + qi) * Ec + h * DKc + tx * 4] = ov;
    }
}

// ---------------------------------------------------------------------------

extern "C" void kernel_launch(void* const* d_in, const int* in_sizes, int n_in,
                              void* d_out, int out_size) {
    const float* query = (const float*)d_in[0];
    const float* key   = (const float*)d_in[1];
    const float* value = (const float*)d_in[2];
    const float* dist  = (const float*)d_in[3];
    const int*   mask  = (const int*)d_in[4];
    const float* Wq = (const float*)d_in[5];
    const float* bq = (const float*)d_in[6];
    const float* Wk = (const float*)d_in[7];
    const float* bk = (const float*)d_in[8];
    const float* Wv = (const float*)d_in[9];
    const float* bv = (const float*)d_in[10];
    const float* Wo = (const float*)d_in[11];
    const float* bo = (const float*)d_in[12];
    const float* cw1 = (const float*)d_in[13];
    const float* cb1 = (const float*)d_in[14];
    const float* cw2 = (const float*)d_in[15];
    const float* cb2 = (const float*)d_in[16];
    float* out = (float*)d_out;

    float *Qp, *Kp, *Vp, *Xc;
    cudaGetSymbolAddress((void**)&Qp, g_Q);
    cudaGetSymbolAddress((void**)&Kp, g_K);
    cudaGetSymbolAddress((void**)&Vp, g_V);
    cudaGetSymbolAddress((void**)&Xc, g_X);

    const dim3 ggrid(Ec / 64, M_TOT / 64);
    gemm_proj<true><<<ggrid, 256>>>(query, Wq, bq, Qp);
    gemm_proj<true><<<ggrid, 256>>>(key, Wk, bk, Kp);
    gemm_proj<true><<<ggrid, 256>>>(value, Wv, bv, Vp);

    const int smem = 4 * 64 * 65 * (int)sizeof(float);  // 66560 B
    cudaFuncSetAttribute(attn_kernel, cudaFuncAttributeMaxDynamicSharedMemorySize, smem);
    attn_kernel<<<dim3(Sc / 64, Hc, Bc), 256, smem>>>(Qp, Kp, Vp, dist, mask,
                                                      cw1, cb1, cw2, cb2, Xc);

    gemm_proj<false><<<ggrid, 256>>>(Xc, Wo, bo, out);
}

// round 3
// speedup vs baseline: 1.1047x; 1.1047x over previous
#include <cuda_runtime.h>
#include <math.h>

namespace {
constexpr int Bc = 4, Sc = 1024, Ec = 512, Hc = 8, DKc = 64;
constexpr int M_TOT = Bc * Sc;  // 4096
}

// Scratch (device globals: allocation-free per harness rules)
__device__ float g_Q[(size_t)Bc * Hc * Sc * DKc];
__device__ float g_K[(size_t)Bc * Hc * Sc * DKc];
__device__ float g_V[(size_t)Bc * Hc * Sc * DKc];
__device__ float g_X[(size_t)Bc * Sc * Ec];

// ---- packed fp32x2 helpers (B300 FFMA2: only reachable via PTX) ------------
__device__ __forceinline__ void fma2(unsigned long long& d, unsigned long long a,
                                     unsigned long long b) {
    asm("fma.rn.f32x2 %0, %1, %2, %0;" : "+l"(d) : "l"(a), "l"(b));
}
__device__ __forceinline__ void mul2(unsigned long long& d, unsigned long long a) {
    asm("mul.rn.f32x2 %0, %0, %1;" : "+l"(d) : "l"(a));
}
__device__ __forceinline__ unsigned long long bc2(float x) {
    unsigned long long r;
    asm("mov.b64 %0, {%1, %1};" : "=l"(r) : "f"(x));
    return r;
}
__device__ __forceinline__ float2 up2(unsigned long long v) {
    float2 f;
    asm("mov.b64 {%0, %1}, %2;" : "=f"(f.x), "=f"(f.y) : "l"(v));
    return f;
}

// chunk swizzle: 16B chunks XORed by row bits -> conflict-free row AND
// column-of-rows LDS.128 access in a [64][64] fp32 tile.
__device__ __forceinline__ int SWZ(int r, int c) { return c ^ (((r >> 2) & 7) << 2); }

// ---------------------------------------------------------------------------
// GEMM body: Y = X * W^T + bias. X:[M,E], W:[N,K]=[E,E] row-major.
// 64x64 tile, BK=64, 4x4 micro-tile, FFMA2 packed over k-parity.
// ---------------------------------------------------------------------------
template <bool SPLIT>
__device__ __forceinline__ void gemm_body(const float* __restrict__ X,
                                          const float* __restrict__ W,
                                          const float* __restrict__ bias,
                                          float* __restrict__ Y) {
    __shared__ float Xs[64 * 64];
    __shared__ float Ws[64 * 64];
    const int tid = threadIdx.x;
    const int tx = tid & 15, ty = tid >> 4;
    const int bm = blockIdx.y * 64, bn = blockIdx.x * 64;

    unsigned long long acc[4][4] = {};

    for (int k0 = 0; k0 < Ec; k0 += 64) {
#pragma unroll
        for (int t = 0; t < 4; t++) {
            int idx = t * 256 + tid;  // 1024 float4 slots per tile
            int r = idx >> 4, c = (idx & 15) << 2;
            *(float4*)&Xs[r * 64 + SWZ(r, c)] =
                *(const float4*)&X[(size_t)(bm + r) * Ec + k0 + c];
            *(float4*)&Ws[r * 64 + SWZ(r, c)] =
                *(const float4*)&W[(size_t)(bn + r) * Ec + k0 + c];
        }
        __syncthreads();
#pragma unroll
        for (int k = 0; k < 64; k += 4) {
            ulonglong2 a[4], w[4];
#pragma unroll
            for (int i = 0; i < 4; i++)
                a[i] = *(const ulonglong2*)&Xs[(ty * 4 + i) * 64 + SWZ(ty * 4 + i, k)];
#pragma unroll
            for (int j = 0; j < 4; j++)
                w[j] = *(const ulonglong2*)&Ws[(tx * 4 + j) * 64 + SWZ(tx * 4 + j, k)];
#pragma unroll
            for (int i = 0; i < 4; i++)
#pragma unroll
                for (int j = 0; j < 4; j++) {
                    fma2(acc[i][j], a[i].x, w[j].x);
                    fma2(acc[i][j], a[i].y, w[j].y);
                }
        }
        __syncthreads();
    }

    const int n0 = bn + tx * 4;
    const float4 bv = *(const float4*)&bias[n0];
#pragma unroll
    for (int i = 0; i < 4; i++) {
        const int m = bm + ty * 4 + i;
        float2 p0 = up2(acc[i][0]), p1 = up2(acc[i][1]);
        float2 p2 = up2(acc[i][2]), p3 = up2(acc[i][3]);
        float4 o;
        o.x = p0.x + p0.y + bv.x;
        o.y = p1.x + p1.y + bv.y;
        o.z = p2.x + p2.y + bv.z;
        o.w = p3.x + p3.y + bv.w;
        if (SPLIT) {
            const int bIdx = m >> 10, s = m & (Sc - 1);
            const int h = n0 >> 6, d = n0 & 63;
            *(float4*)&Y[(((size_t)bIdx * Hc + h) * Sc + s) * DKc + d] = o;
        } else {
            *(float4*)&Y[(size_t)m * Ec + n0] = o;
        }
    }
}

// fused Q/K/V projections: blockIdx.z selects which projection
__global__ void __launch_bounds__(256, 2) gemm_qkv(
    const float* __restrict__ Xq, const float* __restrict__ Xk,
    const float* __restrict__ Xv, const float* __restrict__ Wq,
    const float* __restrict__ Wk, const float* __restrict__ Wv,
    const float* __restrict__ bq, const float* __restrict__ bk,
    const float* __restrict__ bv, float* __restrict__ Yq, float* __restrict__ Yk,
    float* __restrict__ Yv) {
    const int z = blockIdx.z;
    const float* X = (z == 0) ? Xq : (z == 1) ? Xk : Xv;
    const float* W = (z == 0) ? Wq : (z == 1) ? Wk : Wv;
    const float* b = (z == 0) ? bq : (z == 1) ? bk : bv;
    float* Y = (z == 0) ? Yq : (z == 1) ? Yk : Yv;
    gemm_body<true>(X, W, b, Y);
}

__global__ void __launch_bounds__(256, 2) gemm_out(const float* __restrict__ X,
                                                   const float* __restrict__ W,
                                                   const float* __restrict__ bias,
                                                   float* __restrict__ Y) {
    gemm_body<false>(X, W, bias, Y);
}

// ---------------------------------------------------------------------------
// Fused flash attention, FFMA2 + swizzled LDS.128.
// grid: (h, q-tile, b) so the 8 heads sharing dist/mask rows run adjacent.
// ---------------------------------------------------------------------------
__global__ void __launch_bounds__(256, 2) attn_kernel(
    const float* __restrict__ Qp, const float* __restrict__ Kp,
    const float* __restrict__ Vp, const float* __restrict__ dist,
    const int* __restrict__ mask, const float* __restrict__ cw1,
    const float* __restrict__ cb1, const float* __restrict__ cw2,
    const float* __restrict__ cb2, float* __restrict__ Xout) {
    extern __shared__ float sm[];
    float* Qs = sm;             // [64][64] swizzled
    float* Ks = sm + 4096;
    float* Vs = sm + 8192;
    float* Ps = sm + 12288;

    const int tid = threadIdx.x;
    const int tx = tid & 15, ty = tid >> 4;
    const int b = blockIdx.z, h = blockIdx.x;
    const int q0 = blockIdx.y * 64;

    const float* Qbase = Qp + ((size_t)b * Hc + h) * Sc * DKc;
    const float* Kbase = Kp + ((size_t)b * Hc + h) * Sc * DKc;
    const float* Vbase = Vp + ((size_t)b * Hc + h) * Sc * DKc;

    float w1[8], b1[8], w2[8];
#pragma unroll
    for (int t = 0; t < 8; t++) {
        w1[t] = cw1[t];
        b1[t] = cb1[t];
        w2[t] = cw2[h * Hc + t];
    }
    const float c2 = cb2[h];

    // load Q tile (64x64), swizzled
#pragma unroll
    for (int t = 0; t < 4; t++) {
        int idx = t * 256 + tid;
        int r = idx >> 4, c = (idx & 15) << 2;
        *(float4*)&Qs[r * 64 + SWZ(r, c)] =
            *(const float4*)&Qbase[(size_t)(q0 + r) * DKc + c];
    }

    unsigned long long o[4][2] = {};  // packed over output columns
    float mrow[4], lrow[4];
#pragma unroll
    for (int i = 0; i < 4; i++) { mrow[i] = -INFINITY; lrow[i] = 0.f; }

    for (int k0 = 0; k0 < Sc; k0 += 64) {
        __syncthreads();  // prior-iter Ks/Vs reads complete (also covers Q load)
#pragma unroll
        for (int t = 0; t < 4; t++) {
            int idx = t * 256 + tid;
            int r = idx >> 4, c = (idx & 15) << 2;
            *(float4*)&Ks[r * 64 + SWZ(r, c)] =
                *(const float4*)&Kbase[(size_t)(k0 + r) * DKc + c];
            *(float4*)&Vs[r * 64 + SWZ(r, c)] =
                *(const float4*)&Vbase[(size_t)(k0 + r) * DKc + c];
        }
        __syncthreads();

        // S = Q * K^T : packed over k-parity
        float sc[4][4];
        {
            unsigned long long qk[4][4] = {};
#pragma unroll
            for (int k = 0; k < DKc; k += 4) {
                ulonglong2 aq[4], kk[4];
#pragma unroll
                for (int i = 0; i < 4; i++)
                    aq[i] = *(const ulonglong2*)&Qs[(ty * 4 + i) * 64 + SWZ(ty * 4 + i, k)];
#pragma unroll
                for (int j = 0; j < 4; j++)
                    kk[j] = *(const ulonglong2*)&Ks[(tx * 4 + j) * 64 + SWZ(tx * 4 + j, k)];
#pragma unroll
                for (int i = 0; i < 4; i++)
#pragma unroll
                    for (int j = 0; j < 4; j++) {
                        fma2(qk[i][j], aq[i].x, kk[j].x);
                        fma2(qk[i][j], aq[i].y, kk[j].y);
                    }
            }
#pragma unroll
            for (int i = 0; i < 4; i++)
#pragma unroll
                for (int j = 0; j < 4; j++) {
                    float2 f = up2(qk[i][j]);
                    sc[i][j] = f.x + f.y;
                }
        }

        // scale * bias, mask
#pragma unroll
        for (int i = 0; i < 4; i++) {
            const int qi = q0 + ty * 4 + i;
            const size_t rowoff = ((size_t)b * Sc + qi) * Sc + k0 + tx * 4;
            float4 dv = *(const float4*)&dist[rowoff];
            int4 mv = *(const int4*)&mask[rowoff];
            float dd[4] = {dv.x, dv.y, dv.z, dv.w};
            int mm[4] = {mv.x, mv.y, mv.z, mv.w};
#pragma unroll
            for (int j = 0; j < 4; j++) {
                float bias = c2;
#pragma unroll
                for (int t = 0; t < 8; t++)
                    bias += w2[t] * fmaxf(fmaf(dd[j], w1[t], b1[t]), 0.f);
                float sv = sc[i][j] * 0.125f * bias;
                sc[i][j] = (mm[j] == 0) ? -1e9f : sv;
            }
        }

        // online softmax; rows live in one 16-lane group
#pragma unroll
        for (int i = 0; i < 4; i++) {
            float mloc = fmaxf(fmaxf(sc[i][0], sc[i][1]), fmaxf(sc[i][2], sc[i][3]));
#pragma unroll
            for (int off = 8; off >= 1; off >>= 1)
                mloc = fmaxf(mloc, __shfl_xor_sync(0xffffffffu, mloc, off, 16));
            const float mnew = fmaxf(mrow[i], mloc);
            const float alpha = __expf(mrow[i] - mnew);
            mrow[i] = mnew;
            float p0 = __expf(sc[i][0] - mnew);
            float p1 = __expf(sc[i][1] - mnew);
            float p2 = __expf(sc[i][2] - mnew);
            float p3 = __expf(sc[i][3] - mnew);
            float rs = (p0 + p1) + (p2 + p3);
#pragma unroll
            for (int off = 8; off >= 1; off >>= 1)
                rs += __shfl_xor_sync(0xffffffffu, rs, off, 16);
            lrow[i] = lrow[i] * alpha + rs;
            float4 pv = {p0, p1, p2, p3};
            *(float4*)&Ps[(ty * 4 + i) * 64 + SWZ(ty * 4 + i, tx * 4)] = pv;
            unsigned long long av = bc2(alpha);
            mul2(o[i][0], av);
            mul2(o[i][1], av);
        }
        __syncwarp(0xffffffffu);  // P tile is produced/consumed warp-locally

        // O += P * V : packed over output columns
#pragma unroll
        for (int k = 0; k < 64; k += 4) {
            ulonglong2 pr[4], vv[4];
#pragma unroll
            for (int i = 0; i < 4; i++)
                pr[i] = *(const ulonglong2*)&Ps[(ty * 4 + i) * 64 + SWZ(ty * 4 + i, k)];
#pragma unroll
            for (int u = 0; u < 4; u++)
                vv[u] = *(const ulonglong2*)&Vs[(k + u) * 64 + SWZ(k + u, tx * 4)];
#pragma unroll
            for (int i = 0; i < 4; i++) {
                float2 p01 = up2(pr[i].x);
                float2 p23 = up2(pr[i].y);
                unsigned long long w0 = bc2(p01.x), w1p = bc2(p01.y);
                unsigned long long w2p = bc2(p23.x), w3 = bc2(p23.y);
                fma2(o[i][0], w0, vv[0].x);  fma2(o[i][1], w0, vv[0].y);
                fma2(o[i][0], w1p, vv[1].x); fma2(o[i][1], w1p, vv[1].y);
                fma2(o[i][0], w2p, vv[2].x); fma2(o[i][1], w2p, vv[2].y);
                fma2(o[i][0], w3, vv[3].x);  fma2(o[i][1], w3, vv[3].y);
            }
        }
    }

    // epilogue: normalize, write concatenated [B,S,E]
#pragma unroll
    for (int i = 0; i < 4; i++) {
        const int qi = q0 + ty * 4 + i;
        const float inv = 1.f / lrow[i];
        float2 o01 = up2(o[i][0]);
        float2 o23 = up2(o[i][1]);
        float4 ov = {o01.x * inv, o01.y * inv, o23.x * inv, o23.y * inv};
        *(float4*)&Xout[((size_t)b * Sc + qi) * Ec + h * DKc + tx * 4] = ov;
    }
}

// ---------------------------------------------------------------------------

extern "C" void kernel_launch(void* const* d_in, const int* in_sizes, int n_in,
                              void* d_out, int out_size) {
    const float* query = (const float*)d_in[0];
    const float* key   = (const float*)d_in[1];
    const float* value = (const float*)d_in[2];
    const float* dist  = (const float*)d_in[3];
    const int*   mask  = (const int*)d_in[4];
    const float* Wq = (const float*)d_in[5];
    const float* bq = (const float*)d_in[6];
    const float* Wk = (const float*)d_in[7];
    const float* bk = (const float*)d_in[8];
    const float* Wv = (const float*)d_in[9];
    const float* bv = (const float*)d_in[10];
    const float* Wo = (const float*)d_in[11];
    const float* bo = (const float*)d_in[12];
    const float* cw1 = (const float*)d_in[13];
    const float* cb1 = (const float*)d_in[14];
    const float* cw2 = (const float*)d_in[15];
    const float* cb2 = (const float*)d_in[16];
    float* out = (float*)d_out;

    float *Qp, *Kp, *Vp, *Xc;
    cudaGetSymbolAddress((void**)&Qp, g_Q);
    cudaGetSymbolAddress((void**)&Kp, g_K);
    cudaGetSymbolAddress((void**)&Vp, g_V);
    cudaGetSymbolAddress((void**)&Xc, g_X);

    gemm_qkv<<<dim3(Ec / 64, M_TOT / 64, 3), 256>>>(query, key, value, Wq, Wk, Wv,
                                                    bq, bk, bv, Qp, Kp, Vp);

    const int smem = 4 * 64 * 64 * (int)sizeof(float);  // 65536 B
    cudaFuncSetAttribute(attn_kernel, cudaFuncAttributeMaxDynamicSharedMemorySize, smem);
    attn_kernel<<<dim3(Hc, Sc / 64, Bc), 256, smem>>>(Qp, Kp, Vp, dist, mask, cw1,
                                                      cb1, cw2, cb2, Xc);

    gemm_out<<<dim3(Ec / 64, M_TOT / 64, 1), 256>>>(Xc, Wo, bo, out);
}